// round 1
// baseline (speedup 1.0000x reference)
#include <cuda_runtime.h>
#include <cstdint>

#define B_ 4
#define S_ 2048
#define E_ 1024
#define H_ 16
#define D_ 64
#define L_ 4
#define M_ (B_*S_)          // 8192 rows
#define PW_ (S_/32)         // 64 mask words per row
#define SCALE_ 0.03125f     // E^-0.5
#define EPS_ 1e-5f

// Scratch (allocation-free rule: __device__ globals)
__device__ float g_x[M_*E_];
__device__ float g_q[M_*E_];
__device__ float g_k[M_*E_];
__device__ float g_v[M_*E_];
__device__ float g_att[M_*E_];
__device__ float g_proj[M_*E_];
__device__ unsigned g_pmask[B_*S_*PW_];

// ---------------------------------------------------------------------------
// Pack mask (int32 0/1 -> bitmask). Shared across heads AND layers.
// ---------------------------------------------------------------------------
__global__ void pack_mask_kernel(const int* __restrict__ mask) {
    unsigned i = blockIdx.x * 256u + threadIdx.x;
    unsigned word = __ballot_sync(0xffffffffu, mask[i] == 1);
    if ((threadIdx.x & 31) == 0) g_pmask[i >> 5] = word;
}

// ---------------------------------------------------------------------------
// C[M_ x E_] = A[M_ x E_] @ W[E_ x E_] + bias.  128x128x16 tile, 8x8/thread.
// ---------------------------------------------------------------------------
__global__ __launch_bounds__(256, 2)
void gemm_bias_kernel(const float* __restrict__ A, const float* __restrict__ W,
                      const float* __restrict__ bias, float* __restrict__ C) {
    __shared__ float As[16][128];
    __shared__ float Ws[16][128];
    const int tid = threadIdx.x;
    const int bm = blockIdx.y, bn = blockIdx.x;
    const int ty = tid >> 4, tx = tid & 15;
    const float* Ap = A + (size_t)bm * 128 * E_;
    const float* Wp = W + bn * 128;
    float acc[8][8] = {};
    for (int kt = 0; kt < E_; kt += 16) {
        #pragma unroll
        for (int i = 0; i < 2; i++) {
            int idx = tid + i * 256;
            int r = idx >> 2, c = (idx & 3) << 2;
            float4 a = *(const float4*)(Ap + (size_t)r * E_ + kt + c);
            As[c+0][r] = a.x; As[c+1][r] = a.y; As[c+2][r] = a.z; As[c+3][r] = a.w;
            int rw = idx >> 5, cw = (idx & 31) << 2;
            *(float4*)&Ws[rw][cw] = *(const float4*)(Wp + (size_t)(kt + rw) * E_ + cw);
        }
        __syncthreads();
        #pragma unroll
        for (int k = 0; k < 16; k++) {
            float a[8], b[8];
            *(float4*)(a)   = *(float4*)&As[k][ty*8];
            *(float4*)(a+4) = *(float4*)&As[k][ty*8+4];
            *(float4*)(b)   = *(float4*)&Ws[k][tx*8];
            *(float4*)(b+4) = *(float4*)&Ws[k][tx*8+4];
            #pragma unroll
            for (int i = 0; i < 8; i++)
                #pragma unroll
                for (int j = 0; j < 8; j++)
                    acc[i][j] = fmaf(a[i], b[j], acc[i][j]);
        }
        __syncthreads();
    }
    float bv[8];
    *(float4*)(bv)   = *(const float4*)(bias + bn*128 + tx*8);
    *(float4*)(bv+4) = *(const float4*)(bias + bn*128 + tx*8 + 4);
    #pragma unroll
    for (int i = 0; i < 8; i++) {
        size_t row = (size_t)bm*128 + ty*8 + i;
        float4 o0, o1;
        o0.x = acc[i][0]+bv[0]; o0.y = acc[i][1]+bv[1];
        o0.z = acc[i][2]+bv[2]; o0.w = acc[i][3]+bv[3];
        o1.x = acc[i][4]+bv[4]; o1.y = acc[i][5]+bv[5];
        o1.z = acc[i][6]+bv[6]; o1.w = acc[i][7]+bv[7];
        *(float4*)(C + row*E_ + bn*128 + tx*8)     = o0;
        *(float4*)(C + row*E_ + bn*128 + tx*8 + 4) = o1;
    }
}

// ---------------------------------------------------------------------------
// Fused ReLU attention: per (b,h,q-tile of 128), stream 128-wide kv blocks.
// Stage 1: S = Q@K^T (masked relu, scaled) into smem (transposed, pad 129).
// Stage 2: O += S@V. Energy tensor never touches HBM.
// ---------------------------------------------------------------------------
#define PQ_ 132   // Qt/Kt row stride (pad: transpose STS 8-way instead of 16-way)
#define PS_ 129   // Ss row stride (odd: scalar reads conflict-free, STS 4-way)

__global__ __launch_bounds__(256, 1)
void relu_attn_kernel(const float* __restrict__ q, const float* __restrict__ k,
                      const float* __restrict__ v, float* __restrict__ o) {
    extern __shared__ float sm[];
    float* Qt = sm;                       // [64][PQ_]  d-major
    float* Kt = Qt + 64*PQ_;              // [64][PQ_]
    float* Vs = Kt + 64*PQ_;              // [128][64]  row-major
    float* Ss = Vs + 128*64;              // [128][PS_] scores, [kv][q]
    const int tid = threadIdx.x;
    const int qt = blockIdx.x, h = blockIdx.y, b = blockIdx.z;
    const int q0 = qt * 128;
    const float* qb = q + ((size_t)b*S_)*E_ + h*D_;
    const float* kb = k + ((size_t)b*S_)*E_ + h*D_;
    const float* vb = v + ((size_t)b*S_)*E_ + h*D_;
    const unsigned* pm = g_pmask + (size_t)b*S_*PW_;

    // Load Q tile transposed (once per block)
    #pragma unroll
    for (int i = 0; i < 8; i++) {
        int idx = tid + i*256;
        int r = idx >> 4, c = (idx & 15) << 2;
        float4 a = *(const float4*)(qb + (size_t)(q0 + r)*E_ + c);
        Qt[(c+0)*PQ_ + r] = a.x; Qt[(c+1)*PQ_ + r] = a.y;
        Qt[(c+2)*PQ_ + r] = a.z; Qt[(c+3)*PQ_ + r] = a.w;
    }

    const int ty = tid >> 4, tx = tid & 15;   // stage 1: i0=ty*8, j0=tx*8
    const int rg = tid >> 3, cg = tid & 7;    // stage 2: i0=rg*4, d0=cg*8
    float oacc[4][8] = {};

    for (int k0 = 0; k0 < S_; k0 += 128) {
        __syncthreads();   // prev stage2 done reading Kt/Vs/Ss; Qt writes visible
        #pragma unroll
        for (int i = 0; i < 8; i++) {
            int idx = tid + i*256;
            int r = idx >> 4, c = (idx & 15) << 2;
            float4 a = *(const float4*)(kb + (size_t)(k0 + r)*E_ + c);
            Kt[(c+0)*PQ_ + r] = a.x; Kt[(c+1)*PQ_ + r] = a.y;
            Kt[(c+2)*PQ_ + r] = a.z; Kt[(c+3)*PQ_ + r] = a.w;
            *(float4*)&Vs[r*64 + c] = *(const float4*)(vb + (size_t)(k0 + r)*E_ + c);
        }
        __syncthreads();

        // Stage 1: 128x128 scores, 8x8 per thread over d=64
        float acc[8][8] = {};
        #pragma unroll 8
        for (int d = 0; d < 64; d++) {
            float a[8], bb[8];
            *(float4*)(a)    = *(float4*)&Qt[d*PQ_ + ty*8];
            *(float4*)(a+4)  = *(float4*)&Qt[d*PQ_ + ty*8 + 4];
            *(float4*)(bb)   = *(float4*)&Kt[d*PQ_ + tx*8];
            *(float4*)(bb+4) = *(float4*)&Kt[d*PQ_ + tx*8 + 4];
            #pragma unroll
            for (int i = 0; i < 8; i++)
                #pragma unroll
                for (int j = 0; j < 8; j++)
                    acc[i][j] = fmaf(a[i], bb[j], acc[i][j]);
        }
        // mask + relu + scale; write transposed [kv][q]
        const unsigned sh = (unsigned)((tx*8) & 31);
        const int wofs = (k0 + tx*8) >> 5;
        #pragma unroll
        for (int ii = 0; ii < 8; ii++) {
            unsigned mword = pm[(size_t)(q0 + ty*8 + ii)*PW_ + wofs];
            #pragma unroll
            for (int jj = 0; jj < 8; jj++) {
                float val = fmaxf(acc[ii][jj] * SCALE_, 0.0f);
                if ((mword >> (sh + jj)) & 1u) val = 0.0f;  // masked -> relu(-1e-8*s)=0
                Ss[(tx*8 + jj)*PS_ + ty*8 + ii] = val;
            }
        }
        __syncthreads();

        // Stage 2: O[128x64] += S^T-layout @ V, 4x8 per thread over kv=128
        #pragma unroll 8
        for (int j = 0; j < 128; j++) {
            float s0 = Ss[j*PS_ + rg*4 + 0];
            float s1 = Ss[j*PS_ + rg*4 + 1];
            float s2 = Ss[j*PS_ + rg*4 + 2];
            float s3 = Ss[j*PS_ + rg*4 + 3];
            float vv[8];
            *(float4*)(vv)   = *(float4*)&Vs[j*64 + cg*8];
            *(float4*)(vv+4) = *(float4*)&Vs[j*64 + cg*8 + 4];
            #pragma unroll
            for (int dd = 0; dd < 8; dd++) {
                oacc[0][dd] = fmaf(s0, vv[dd], oacc[0][dd]);
                oacc[1][dd] = fmaf(s1, vv[dd], oacc[1][dd]);
                oacc[2][dd] = fmaf(s2, vv[dd], oacc[2][dd]);
                oacc[3][dd] = fmaf(s3, vv[dd], oacc[3][dd]);
            }
        }
    }
    float* ob = o + ((size_t)b*S_)*E_ + h*D_;
    #pragma unroll
    for (int ii = 0; ii < 4; ii++) {
        size_t row = (size_t)(q0 + rg*4 + ii);
        *(float4*)(ob + row*E_ + cg*8)     = *(float4*)&oacc[ii][0];
        *(float4*)(ob + row*E_ + cg*8 + 4) = *(float4*)&oacc[ii][4];
    }
}

// ---------------------------------------------------------------------------
// out = LayerNorm(a + x) * gamma + beta, one block per row (E=1024)
// ---------------------------------------------------------------------------
__global__ __launch_bounds__(256)
void add_ln_kernel(const float* __restrict__ a, const float* __restrict__ x,
                   const float* __restrict__ gamma, const float* __restrict__ beta,
                   float* __restrict__ out) {
    __shared__ float red[8];
    __shared__ float bcast;
    const int row = blockIdx.x, tid = threadIdx.x;
    const int lane = tid & 31, wid = tid >> 5;
    const float* ap = a + (size_t)row * E_;
    const float* xp = x + (size_t)row * E_;
    float4 va = *(const float4*)(ap + tid*4);
    float4 vx = *(const float4*)(xp + tid*4);
    float v0 = va.x + vx.x, v1 = va.y + vx.y, v2 = va.z + vx.z, v3 = va.w + vx.w;
    float s = v0 + v1 + v2 + v3;
    #pragma unroll
    for (int off = 16; off > 0; off >>= 1) s += __shfl_xor_sync(~0u, s, off);
    if (lane == 0) red[wid] = s;
    __syncthreads();
    if (tid == 0) {
        float t = 0;
        #pragma unroll
        for (int i = 0; i < 8; i++) t += red[i];
        bcast = t;
    }
    __syncthreads();
    float mean = bcast * (1.0f / E_);
    float d0 = v0-mean, d1 = v1-mean, d2 = v2-mean, d3 = v3-mean;
    float vs = d0*d0 + d1*d1 + d2*d2 + d3*d3;
    #pragma unroll
    for (int off = 16; off > 0; off >>= 1) vs += __shfl_xor_sync(~0u, vs, off);
    __syncthreads();
    if (lane == 0) red[wid] = vs;
    __syncthreads();
    if (tid == 0) {
        float t = 0;
        #pragma unroll
        for (int i = 0; i < 8; i++) t += red[i];
        bcast = t;
    }
    __syncthreads();
    float inv = rsqrtf(bcast * (1.0f / E_) + EPS_);
    float4 g  = *(const float4*)(gamma + tid*4);
    float4 bt = *(const float4*)(beta  + tid*4);
    float4 o;
    o.x = d0*inv*g.x + bt.x; o.y = d1*inv*g.y + bt.y;
    o.z = d2*inv*g.z + bt.z; o.w = d3*inv*g.w + bt.w;
    *(float4*)(out + (size_t)row*E_ + tid*4) = o;
}

// ---------------------------------------------------------------------------
extern "C" void kernel_launch(void* const* d_in, const int* in_sizes, int n_in,
                              void* d_out, int out_size) {
    const float* query = (const float*)d_in[0];
    const float* value = (const float*)d_in[1];
    const int*   mask  = (const int*)d_in[2];
    const float* Wq = (const float*)d_in[3];
    const float* Wk = (const float*)d_in[4];
    const float* Wv = (const float*)d_in[5];
    const float* Wo = (const float*)d_in[6];
    const float* bq = (const float*)d_in[7];
    const float* bk = (const float*)d_in[8];
    const float* bv = (const float*)d_in[9];
    const float* bo = (const float*)d_in[10];
    const float* gamma = (const float*)d_in[11];
    const float* beta  = (const float*)d_in[12];
    float* out = (float*)d_out;

    float *x, *qb, *kb, *vb, *att, *proj;
    cudaGetSymbolAddress((void**)&x,    g_x);
    cudaGetSymbolAddress((void**)&qb,   g_q);
    cudaGetSymbolAddress((void**)&kb,   g_k);
    cudaGetSymbolAddress((void**)&vb,   g_v);
    cudaGetSymbolAddress((void**)&att,  g_att);
    cudaGetSymbolAddress((void**)&proj, g_proj);

    const size_t smem = (size_t)(2*64*PQ_ + 128*64 + 128*PS_) * sizeof(float);
    cudaFuncSetAttribute(relu_attn_kernel,
                         cudaFuncAttributeMaxDynamicSharedMemorySize, (int)smem);

    cudaMemcpyAsync(x, query, sizeof(float)*(size_t)M_*E_, cudaMemcpyDeviceToDevice);
    pack_mask_kernel<<<(B_*S_*S_)/256, 256>>>(mask);

    dim3 ggrid(E_/128, M_/128);   // (8, 64)
    dim3 agrid(S_/128, H_, B_);   // (16, 16, 4)
    for (int l = 0; l < L_; l++) {
        const float* Wql = Wq + (size_t)l*E_*E_;
        const float* Wkl = Wk + (size_t)l*E_*E_;
        const float* Wvl = Wv + (size_t)l*E_*E_;
        const float* Wol = Wo + (size_t)l*E_*E_;
        gemm_bias_kernel<<<ggrid, 256>>>(x,     Wql, bq + l*E_, qb);
        gemm_bias_kernel<<<ggrid, 256>>>(value, Wkl, bk + l*E_, kb);
        gemm_bias_kernel<<<ggrid, 256>>>(value, Wvl, bv + l*E_, vb);
        relu_attn_kernel<<<agrid, 256, smem>>>(qb, kb, vb, att);
        gemm_bias_kernel<<<ggrid, 256>>>(att, Wol, bo + l*E_, proj);
        add_ln_kernel<<<M_, 256>>>(proj, x, gamma + l*E_, beta + l*E_,
                                   (l == L_-1) ? out : x);
    }
}

// round 3
// speedup vs baseline: 3.3089x; 3.3089x over previous
#include <cuda_runtime.h>
#include <cuda_bf16.h>
#include <cstdint>

#define B_ 4
#define S_ 2048
#define E_ 1024
#define H_ 16
#define D_ 64
#define L_ 4
#define M_ (B_*S_)          // 8192 rows
#define PW_ (S_/32)         // 64 mask words per row
#define SCALE_ 0.03125f     // E^-0.5
#define EPS_ 1e-5f

// ---------------- scratch (__device__ globals: allocation-free rule) -------
__device__ float g_x[M_*E_];
__device__ float g_proj[M_*E_];
__device__ unsigned g_pmask[B_*S_*PW_];
__device__ __nv_bfloat16 g_xh[M_*E_],  g_xl[M_*E_];
__device__ __nv_bfloat16 g_qh[M_*E_],  g_ql[M_*E_];
__device__ __nv_bfloat16 g_kh[M_*E_],  g_kl[M_*E_];
__device__ __nv_bfloat16 g_vh[M_*E_],  g_vl[M_*E_];
__device__ __nv_bfloat16 g_ath[M_*E_], g_atl[M_*E_];
__device__ __nv_bfloat16 g_vih[M_*E_], g_vil[M_*E_];
__device__ __nv_bfloat16 g_wh[L_*4*E_*E_];   // weights [N][K] (transposed), bf16 hi
__device__ __nv_bfloat16 g_wl[L_*4*E_*E_];   // bf16 lo

// ============================ portable PTX helpers ==========================
__device__ __forceinline__ uint32_t smem_to_u32(const void* p) {
    uint32_t a;
    asm("{ .reg .u64 t; cvta.to.shared.u64 t, %1; cvt.u32.u64 %0, t; }"
        : "=r"(a) : "l"(p));
    return a;
}
#define SMEM_SWIZZLE_128B(o) ((o) ^ (((o) >> 3) & 0x70))

__device__ __forceinline__ void cp16(uint32_t dst, const void* src) {
    asm volatile("cp.async.cg.shared.global [%0], [%1], 16;" :: "r"(dst), "l"(src) : "memory");
}
#define CP_COMMIT() asm volatile("cp.async.commit_group;" ::: "memory")
#define CP_WAIT1()  asm volatile("cp.async.wait_group 1;" ::: "memory")
#define CP_WAIT0()  asm volatile("cp.async.wait_group 0;" ::: "memory")

__device__ __forceinline__ void ldsm4(uint32_t* r, uint32_t a) {
    asm volatile("ldmatrix.sync.aligned.m8n8.x4.shared.b16 {%0,%1,%2,%3}, [%4];"
        : "=r"(r[0]), "=r"(r[1]), "=r"(r[2]), "=r"(r[3]) : "r"(a));
}
__device__ __forceinline__ void ldsm4t(uint32_t* r, uint32_t a) {
    asm volatile("ldmatrix.sync.aligned.m8n8.x4.trans.shared.b16 {%0,%1,%2,%3}, [%4];"
        : "=r"(r[0]), "=r"(r[1]), "=r"(r[2]), "=r"(r[3]) : "r"(a));
}
// D += A(16x16) * B(16x8), bf16 in, fp32 accum
__device__ __forceinline__ void mma_bf16(float* c, const uint32_t* a, const uint32_t* b) {
    asm volatile("mma.sync.aligned.m16n8k16.row.col.f32.bf16.bf16.f32 "
        "{%0,%1,%2,%3}, {%4,%5,%6,%7}, {%8,%9}, {%0,%1,%2,%3};"
        : "+f"(c[0]), "+f"(c[1]), "+f"(c[2]), "+f"(c[3])
        : "r"(a[0]), "r"(a[1]), "r"(a[2]), "r"(a[3]), "r"(b[0]), "r"(b[1]));
}
__device__ __forceinline__ void split2(float v0, float v1, uint32_t& hi, uint32_t& lo) {
    __nv_bfloat16 h0 = __float2bfloat16(v0), h1 = __float2bfloat16(v1);
    __nv_bfloat16 l0 = __float2bfloat16(v0 - __bfloat162float(h0));
    __nv_bfloat16 l1 = __float2bfloat16(v1 - __bfloat162float(h1));
    __nv_bfloat162 Hh, Ll;
    Hh.x = h0; Hh.y = h1; Ll.x = l0; Ll.y = l1;
    hi = *(uint32_t*)&Hh; lo = *(uint32_t*)&Ll;
}

// ---------------------------------------------------------------------------
// Pack mask bits (shared across heads AND layers)
// ---------------------------------------------------------------------------
__global__ void pack_mask_kernel(const int* __restrict__ mask) {
    unsigned i = blockIdx.x * 256u + threadIdx.x;
    unsigned word = __ballot_sync(0xffffffffu, mask[i] == 1);
    if ((threadIdx.x & 31) == 0) g_pmask[i >> 5] = word;
}

// ---------------------------------------------------------------------------
// fp32 -> bf16 hi/lo split (same layout)
// ---------------------------------------------------------------------------
__global__ void split_act_kernel(const float* __restrict__ src,
                                 __nv_bfloat16* __restrict__ hi,
                                 __nv_bfloat16* __restrict__ lo) {
    size_t i = (size_t)blockIdx.x * 256 + threadIdx.x;
    float4 v = ((const float4*)src)[i];
    uint32_t h01, l01, h23, l23;
    split2(v.x, v.y, h01, l01);
    split2(v.z, v.w, h23, l23);
    ((uint2*)hi)[i] = make_uint2(h01, h23);
    ((uint2*)lo)[i] = make_uint2(l01, l23);
}

// ---------------------------------------------------------------------------
// Weight split + transpose: out[n][k] = W[k][n] as bf16 hi/lo.
// ---------------------------------------------------------------------------
__global__ void split_wT_kernel(const float* __restrict__ Wbase,
                                __nv_bfloat16* __restrict__ hibase,
                                __nv_bfloat16* __restrict__ lobase, int slot) {
    __shared__ float t[32][33];
    const float* W = Wbase + (size_t)blockIdx.z * E_ * E_;
    size_t dofs = (((size_t)blockIdx.z * 4) + slot) << 20;   // E_*E_ = 1<<20
    __nv_bfloat16* hi = hibase + dofs;
    __nv_bfloat16* lo = lobase + dofs;
    int bn = blockIdx.x * 32, bk = blockIdx.y * 32;
    int tx = threadIdx.x, ty = threadIdx.y;
    #pragma unroll
    for (int i = 0; i < 32; i += 8)
        t[ty + i][tx] = W[(size_t)(bk + ty + i) * E_ + bn + tx];
    __syncthreads();
    #pragma unroll
    for (int i = 0; i < 32; i += 8) {
        float x = t[tx][ty + i];
        __nv_bfloat16 h = __float2bfloat16(x);
        __nv_bfloat16 l = __float2bfloat16(x - __bfloat162float(h));
        size_t o = (size_t)(bn + ty + i) * E_ + bk + tx;
        hi[o] = h; lo[o] = l;
    }
}

// ---------------------------------------------------------------------------
// bf16x3 MMA GEMM: C[8192x1024] = (Ah+Al) @ (Wh+Wl)^T + bias ; W is [N][K].
// CTA 128x128, 8 warps @ 64x32, K-chunk 64, cp.async double-buffered.
// OUT_BF16=1: write bf16 hi/lo split; else fp32.
// ---------------------------------------------------------------------------
#define GSTAGE 65536   // Ah 0 | Al 16K | Wh 32K | Wl 48K (each 128x64 bf16 = 16KB)

__device__ __forceinline__ void gemm_load_stage(uint32_t base,
        const char* gA_h, const char* gA_l, const char* gW_h, const char* gW_l,
        int kc, int tid) {
    size_t co = (size_t)kc * 128;
    #pragma unroll
    for (int i = 0; i < 4; i++) {
        int idx = tid + i * 256;            // 0..1023 : r = idx>>3, seg = idx&7
        int r = idx >> 3, sg = idx & 7;
        uint32_t so = SMEM_SWIZZLE_128B((uint32_t)(r * 128 + sg * 16));
        size_t go = (size_t)r * 2048 + co + sg * 16;
        cp16(base + so,         gA_h + go);
        cp16(base + 16384 + so, gA_l + go);
        cp16(base + 32768 + so, gW_h + go);
        cp16(base + 49152 + so, gW_l + go);
    }
}

template<int OUT_BF16>
__global__ __launch_bounds__(256, 1)
void gemm_mma(const __nv_bfloat16* __restrict__ Ah, const __nv_bfloat16* __restrict__ Al,
              const __nv_bfloat16* __restrict__ Wh, const __nv_bfloat16* __restrict__ Wl,
              const float* __restrict__ bias,
              float* __restrict__ C,
              __nv_bfloat16* __restrict__ Ch, __nv_bfloat16* __restrict__ Cl) {
    extern __shared__ char smem[];
    const uint32_t sb = smem_to_u32(smem);
    const int tid = threadIdx.x, lane = tid & 31, w = tid >> 5;
    const int bm = blockIdx.y, bn = blockIdx.x;
    const int m0 = (w & 1) * 64, n0 = (w >> 1) * 32;

    const char* gA_h = (const char*)(Ah + (size_t)bm * 128 * E_);
    const char* gA_l = (const char*)(Al + (size_t)bm * 128 * E_);
    const char* gW_h = (const char*)(Wh + (size_t)bn * 128 * E_);
    const char* gW_l = (const char*)(Wl + (size_t)bn * 128 * E_);

    // ldmatrix address components
    const int arow = m0 + (lane & 15);
    const uint32_t a_kb = (uint32_t)((lane >> 4) * 16);
    const uint32_t axor = (uint32_t)((arow & 7) << 4);
    const int brow = n0 + (lane & 7) + ((lane >> 4) << 3);
    const uint32_t b_kb = (uint32_t)(((lane >> 3) & 1) * 16);
    const uint32_t bxor = (uint32_t)((brow & 7) << 4);

    float c[4][4][4];
    #pragma unroll
    for (int i = 0; i < 4; i++)
        #pragma unroll
        for (int j = 0; j < 4; j++)
            #pragma unroll
            for (int q = 0; q < 4; q++) c[i][j][q] = 0.f;

    gemm_load_stage(sb, gA_h, gA_l, gW_h, gW_l, 0, tid);
    CP_COMMIT();

    for (int kc = 0; kc < 16; kc++) {
        uint32_t stg = sb + (uint32_t)((kc & 1) * GSTAGE);
        if (kc + 1 < 16) {
            gemm_load_stage(sb + (uint32_t)(((kc + 1) & 1) * GSTAGE),
                            gA_h, gA_l, gW_h, gW_l, kc + 1, tid);
            CP_COMMIT();
            CP_WAIT1();
        } else {
            CP_WAIT0();
        }
        __syncthreads();
        #pragma unroll
        for (int kk = 0; kk < 4; kk++) {
            uint32_t ah[4][4], al[4][4], bh[2][4], bl[2][4];
            #pragma unroll
            for (int mt = 0; mt < 4; mt++) {
                uint32_t ra = stg + (uint32_t)((arow + mt * 16) * 128)
                                  + (((uint32_t)(kk * 32) + a_kb) ^ axor);
                ldsm4(ah[mt], ra);
                ldsm4(al[mt], ra + 16384);
            }
            #pragma unroll
            for (int hs = 0; hs < 2; hs++) {
                uint32_t rb = stg + 32768 + (uint32_t)((brow + hs * 16) * 128)
                                  + (((uint32_t)(kk * 32) + b_kb) ^ bxor);
                ldsm4(bh[hs], rb);
                ldsm4(bl[hs], rb + 16384);
            }
            #pragma unroll
            for (int mt = 0; mt < 4; mt++)
                #pragma unroll
                for (int nt = 0; nt < 4; nt++) {
                    const uint32_t* bhp = &bh[nt >> 1][(nt & 1) * 2];
                    const uint32_t* blp = &bl[nt >> 1][(nt & 1) * 2];
                    mma_bf16(c[mt][nt], ah[mt], bhp);
                    mma_bf16(c[mt][nt], ah[mt], blp);
                    mma_bf16(c[mt][nt], al[mt], bhp);
                }
        }
        __syncthreads();
    }

    // epilogue
    const int g = lane >> 2, tg = lane & 3;
    #pragma unroll
    for (int nt = 0; nt < 4; nt++) {
        int col = bn * 128 + n0 + nt * 8 + 2 * tg;
        float b0 = bias[col], b1 = bias[col + 1];
        #pragma unroll
        for (int mt = 0; mt < 4; mt++) {
            int row = bm * 128 + m0 + mt * 16 + g;
            float v0 = c[mt][nt][0] + b0, v1 = c[mt][nt][1] + b1;
            float v2 = c[mt][nt][2] + b0, v3 = c[mt][nt][3] + b1;
            size_t i0 = (size_t)row * E_ + col;
            size_t i1 = i0 + (size_t)8 * E_;
            if (OUT_BF16) {
                uint32_t h01, l01, h23, l23;
                split2(v0, v1, h01, l01);
                split2(v2, v3, h23, l23);
                *(uint32_t*)(Ch + i0) = h01; *(uint32_t*)(Cl + i0) = l01;
                *(uint32_t*)(Ch + i1) = h23; *(uint32_t*)(Cl + i1) = l23;
            } else {
                *(float2*)(C + i0) = make_float2(v0, v1);
                *(float2*)(C + i1) = make_float2(v2, v3);
            }
        }
    }
}

// ---------------------------------------------------------------------------
// Fused ReLU attention, bf16x3 MMA. Per block: (q-tile 128, head, batch).
// smem: Q hi/lo 32K | K/V hi/lo double-buffered 128K | S hi/lo 64K = 224K
// ---------------------------------------------------------------------------
#define AQ_H 0
#define AQ_L 16384
#define AKV(s) (32768 + (s) * GSTAGE)     // Kh 0 | Kl 16K | Vh 32K | Vl 48K
#define AS_H 163840
#define AS_L 196608
#define SMEM_ATTN 229376

__device__ __forceinline__ void attn_load_kv(uint32_t base,
        const char* gK_h, const char* gK_l, const char* gV_h, const char* gV_l,
        int kc, int tid) {
    #pragma unroll
    for (int i = 0; i < 4; i++) {
        int idx = tid + i * 256;
        int r = idx >> 3, sg = idx & 7;
        uint32_t so = SMEM_SWIZZLE_128B((uint32_t)(r * 128 + sg * 16));
        size_t go = (size_t)(kc * 128 + r) * 2048 + sg * 16;
        cp16(base + so,         gK_h + go);
        cp16(base + 16384 + so, gK_l + go);
        cp16(base + 32768 + so, gV_h + go);
        cp16(base + 49152 + so, gV_l + go);
    }
}

__global__ __launch_bounds__(256, 1)
void attn_mma(const __nv_bfloat16* __restrict__ qh, const __nv_bfloat16* __restrict__ ql,
              const __nv_bfloat16* __restrict__ kh, const __nv_bfloat16* __restrict__ kl,
              const __nv_bfloat16* __restrict__ vh, const __nv_bfloat16* __restrict__ vl,
              __nv_bfloat16* __restrict__ oh, __nv_bfloat16* __restrict__ ol) {
    extern __shared__ char smem[];
    const uint32_t sb = smem_to_u32(smem);
    const int tid = threadIdx.x, lane = tid & 31, w = tid >> 5;
    const int qt = blockIdx.x, h = blockIdx.y, b = blockIdx.z;
    const int q0 = qt * 128;
    const int g = lane >> 2, tg = lane & 3;

    const size_t hb = ((size_t)b * S_) * E_ + h * D_;
    const char* gQ_h = (const char*)(qh + hb);
    const char* gQ_l = (const char*)(ql + hb);
    const char* gK_h = (const char*)(kh + hb);
    const char* gK_l = (const char*)(kl + hb);
    const char* gV_h = (const char*)(vh + hb);
    const char* gV_l = (const char*)(vl + hb);
    const unsigned* pm = g_pmask + (size_t)b * S_ * PW_;

    // Q tile (once) + chunk0 K/V, one commit group
    #pragma unroll
    for (int i = 0; i < 4; i++) {
        int idx = tid + i * 256;
        int r = idx >> 3, sg = idx & 7;
        uint32_t so = SMEM_SWIZZLE_128B((uint32_t)(r * 128 + sg * 16));
        size_t go = (size_t)(q0 + r) * 2048 + sg * 16;
        cp16(sb + AQ_H + so, gQ_h + go);
        cp16(sb + AQ_L + so, gQ_l + go);
    }
    attn_load_kv(sb + AKV(0), gK_h, gK_l, gV_h, gV_l, 0, tid);
    CP_COMMIT();

    // stage1 warp map: 2x4 (m x n) over 128q x 128kv
    const int m1 = (w & 1) * 64, n1 = (w >> 1) * 32;
    const int arow1 = m1 + (lane & 15);
    const uint32_t akb1 = (uint32_t)((lane >> 4) * 16);
    const uint32_t ax1 = (uint32_t)((arow1 & 7) << 4);
    const int brow1 = n1 + (lane & 7) + ((lane >> 4) << 3);
    const uint32_t bkb1 = (uint32_t)(((lane >> 3) & 1) * 16);
    const uint32_t bx1 = (uint32_t)((brow1 & 7) << 4);
    // stage2 warp map: 4x2 (q x d) over 128q x 64d
    const int m2 = (w >> 1) * 32, n2 = (w & 1) * 32;
    const int arow2 = m2 + (lane & 15);
    const uint32_t akb2 = (uint32_t)((lane >> 4) * 16);
    const uint32_t ax2 = (uint32_t)((arow2 & 7) << 4);
    const int vrow = lane & 15;
    const uint32_t vdb = (uint32_t)((lane >> 4) * 16);

    float c2[2][4][4];
    #pragma unroll
    for (int i = 0; i < 2; i++)
        #pragma unroll
        for (int j = 0; j < 4; j++)
            #pragma unroll
            for (int q = 0; q < 4; q++) c2[i][j][q] = 0.f;

    for (int kc = 0; kc < 16; kc++) {
        uint32_t kv = sb + AKV(kc & 1);
        if (kc + 1 < 16) {
            attn_load_kv(sb + AKV((kc + 1) & 1), gK_h, gK_l, gV_h, gV_l, kc + 1, tid);
            CP_COMMIT();
            CP_WAIT1();
        } else {
            CP_WAIT0();
        }
        __syncthreads();

        // ---- stage 1: scores = Q @ K^T over d=64 ----
        float c1[4][4][4];
        #pragma unroll
        for (int i = 0; i < 4; i++)
            #pragma unroll
            for (int j = 0; j < 4; j++)
                #pragma unroll
                for (int q = 0; q < 4; q++) c1[i][j][q] = 0.f;
        #pragma unroll
        for (int kk = 0; kk < 4; kk++) {
            uint32_t qhf[4][4], qlf[4][4], khf[2][4], klf[2][4];
            #pragma unroll
            for (int mt = 0; mt < 4; mt++) {
                uint32_t ra = sb + AQ_H + (uint32_t)((arow1 + mt * 16) * 128)
                                 + (((uint32_t)(kk * 32) + akb1) ^ ax1);
                ldsm4(qhf[mt], ra);
                ldsm4(qlf[mt], ra + 16384);
            }
            #pragma unroll
            for (int hs = 0; hs < 2; hs++) {
                uint32_t rb = kv + (uint32_t)((brow1 + hs * 16) * 128)
                                 + (((uint32_t)(kk * 32) + bkb1) ^ bx1);
                ldsm4(khf[hs], rb);
                ldsm4(klf[hs], rb + 16384);
            }
            #pragma unroll
            for (int mt = 0; mt < 4; mt++)
                #pragma unroll
                for (int nt = 0; nt < 4; nt++) {
                    const uint32_t* bhp = &khf[nt >> 1][(nt & 1) * 2];
                    const uint32_t* blp = &klf[nt >> 1][(nt & 1) * 2];
                    mma_bf16(c1[mt][nt], qhf[mt], bhp);
                    mma_bf16(c1[mt][nt], qhf[mt], blp);
                    mma_bf16(c1[mt][nt], qlf[mt], bhp);
                }
        }
        // mask + relu + scale -> S hi/lo (swizzled [q][kv] rows of 256B)
        {
            const int wofs = (kc * 128 + n1) >> 5;
            #pragma unroll
            for (int mt = 0; mt < 4; mt++) {
                int r0 = m1 + mt * 16 + g;
                unsigned mw0 = pm[(size_t)(q0 + r0) * PW_ + wofs];
                unsigned mw1 = pm[(size_t)(q0 + r0 + 8) * PW_ + wofs];
                #pragma unroll
                for (int nt = 0; nt < 4; nt++) {
                    int bit = nt * 8 + 2 * tg;
                    int kvloc = n1 + bit;
                    float v0 = ((mw0 >> bit) & 1u)       ? 0.f : fmaxf(c1[mt][nt][0] * SCALE_, 0.f);
                    float v1 = ((mw0 >> (bit + 1)) & 1u) ? 0.f : fmaxf(c1[mt][nt][1] * SCALE_, 0.f);
                    float v2 = ((mw1 >> bit) & 1u)       ? 0.f : fmaxf(c1[mt][nt][2] * SCALE_, 0.f);
                    float v3 = ((mw1 >> (bit + 1)) & 1u) ? 0.f : fmaxf(c1[mt][nt][3] * SCALE_, 0.f);
                    uint32_t h01, l01, h23, l23;
                    split2(v0, v1, h01, l01);
                    split2(v2, v3, h23, l23);
                    uint32_t so = (uint32_t)(r0 * 256) + (((uint32_t)(kvloc * 2)) ^ ((uint32_t)((r0 & 7) << 4)));
                    *(uint32_t*)(smem + AS_H + so) = h01;
                    *(uint32_t*)(smem + AS_L + so) = l01;
                    *(uint32_t*)(smem + AS_H + so + 2048) = h23;   // +8 rows * 256B
                    *(uint32_t*)(smem + AS_L + so + 2048) = l23;
                }
            }
        }
        __syncthreads();

        // ---- stage 2: O += S @ V over kv=128 ----
        #pragma unroll
        for (int kk = 0; kk < 8; kk++) {
            uint32_t shf[2][4], slf[2][4], vhf[2][4], vlf[2][4];
            #pragma unroll
            for (int mt = 0; mt < 2; mt++) {
                uint32_t ra = sb + AS_H + (uint32_t)((arow2 + mt * 16) * 256)
                                 + (((uint32_t)(kk * 32) + akb2) ^ ax2);
                ldsm4(shf[mt], ra);
                ldsm4(slf[mt], ra + 32768);
            }
            #pragma unroll
            for (int hs = 0; hs < 2; hs++) {
                uint32_t off = (uint32_t)((kk * 16 + vrow) * 128)
                             + (uint32_t)((n2 + hs * 16) * 2) + vdb;
                uint32_t rb = kv + 32768 + SMEM_SWIZZLE_128B(off);
                ldsm4t(vhf[hs], rb);
                ldsm4t(vlf[hs], rb + 16384);
            }
            #pragma unroll
            for (int mt = 0; mt < 2; mt++)
                #pragma unroll
                for (int nt = 0; nt < 4; nt++) {
                    const uint32_t* bhp = &vhf[nt >> 1][(nt & 1) * 2];
                    const uint32_t* blp = &vlf[nt >> 1][(nt & 1) * 2];
                    mma_bf16(c2[mt][nt], shf[mt], bhp);
                    mma_bf16(c2[mt][nt], shf[mt], blp);
                    mma_bf16(c2[mt][nt], slf[mt], bhp);
                }
        }
        __syncthreads();
    }

    // epilogue: write O as bf16 hi/lo
    #pragma unroll
    for (int mt = 0; mt < 2; mt++) {
        #pragma unroll
        for (int nt = 0; nt < 4; nt++) {
            int r = q0 + m2 + mt * 16 + g;
            int dc = n2 + nt * 8 + 2 * tg;
            size_t i0 = ((size_t)b * S_ + r) * E_ + h * D_ + dc;
            size_t i1 = i0 + (size_t)8 * E_;
            uint32_t h01, l01, h23, l23;
            split2(c2[mt][nt][0], c2[mt][nt][1], h01, l01);
            split2(c2[mt][nt][2], c2[mt][nt][3], h23, l23);
            *(uint32_t*)(oh + i0) = h01; *(uint32_t*)(ol + i0) = l01;
            *(uint32_t*)(oh + i1) = h23; *(uint32_t*)(ol + i1) = l23;
        }
    }
}

// ---------------------------------------------------------------------------
// out = LayerNorm(a + x)*gamma + beta ; also writes bf16 hi/lo of out
// ---------------------------------------------------------------------------
__global__ __launch_bounds__(256)
void add_ln_kernel(const float* __restrict__ a, const float* __restrict__ x,
                   const float* __restrict__ gamma, const float* __restrict__ beta,
                   float* __restrict__ out,
                   __nv_bfloat16* __restrict__ oh, __nv_bfloat16* __restrict__ ol) {
    __shared__ float red[8];
    __shared__ float bcast;
    const int row = blockIdx.x, tid = threadIdx.x;
    const int lane = tid & 31, wid = tid >> 5;
    const float* ap = a + (size_t)row * E_;
    const float* xp = x + (size_t)row * E_;
    float4 va = *(const float4*)(ap + tid * 4);
    float4 vx = *(const float4*)(xp + tid * 4);
    float v0 = va.x + vx.x, v1 = va.y + vx.y, v2 = va.z + vx.z, v3 = va.w + vx.w;
    float s = v0 + v1 + v2 + v3;
    #pragma unroll
    for (int off = 16; off > 0; off >>= 1) s += __shfl_xor_sync(~0u, s, off);
    if (lane == 0) red[wid] = s;
    __syncthreads();
    if (tid == 0) {
        float t = 0;
        #pragma unroll
        for (int i = 0; i < 8; i++) t += red[i];
        bcast = t;
    }
    __syncthreads();
    float mean = bcast * (1.0f / E_);
    float d0 = v0 - mean, d1 = v1 - mean, d2 = v2 - mean, d3 = v3 - mean;
    float vs = d0*d0 + d1*d1 + d2*d2 + d3*d3;
    #pragma unroll
    for (int off = 16; off > 0; off >>= 1) vs += __shfl_xor_sync(~0u, vs, off);
    __syncthreads();
    if (lane == 0) red[wid] = vs;
    __syncthreads();
    if (tid == 0) {
        float t = 0;
        #pragma unroll
        for (int i = 0; i < 8; i++) t += red[i];
        bcast = t;
    }
    __syncthreads();
    float inv = rsqrtf(bcast * (1.0f / E_) + EPS_);
    float4 gq = *(const float4*)(gamma + tid * 4);
    float4 bt = *(const float4*)(beta + tid * 4);
    float o0 = d0*inv*gq.x + bt.x, o1 = d1*inv*gq.y + bt.y;
    float o2 = d2*inv*gq.z + bt.z, o3 = d3*inv*gq.w + bt.w;
    *(float4*)(out + (size_t)row * E_ + tid * 4) = make_float4(o0, o1, o2, o3);
    uint32_t h01, l01, h23, l23;
    split2(o0, o1, h01, l01);
    split2(o2, o3, h23, l23);
    size_t i0 = (size_t)row * E_ + tid * 4;
    *(uint2*)(oh + i0) = make_uint2(h01, h23);
    *(uint2*)(ol + i0) = make_uint2(l01, l23);
}

// ---------------------------------------------------------------------------
extern "C" void kernel_launch(void* const* d_in, const int* in_sizes, int n_in,
                              void* d_out, int out_size) {
    const float* query = (const float*)d_in[0];
    const float* value = (const float*)d_in[1];
    const int*   mask  = (const int*)d_in[2];
    const float* Wq = (const float*)d_in[3];
    const float* Wk = (const float*)d_in[4];
    const float* Wv = (const float*)d_in[5];
    const float* Wo = (const float*)d_in[6];
    const float* bq = (const float*)d_in[7];
    const float* bk = (const float*)d_in[8];
    const float* bv = (const float*)d_in[9];
    const float* bo = (const float*)d_in[10];
    const float* gamma = (const float*)d_in[11];
    const float* beta  = (const float*)d_in[12];
    float* out = (float*)d_out;

    float *x, *proj;
    cudaGetSymbolAddress((void**)&x,    g_x);
    cudaGetSymbolAddress((void**)&proj, g_proj);
    __nv_bfloat16 *xh, *xl, *qh, *ql, *kh, *kl, *vh, *vl, *ath, *atl, *vih, *vil, *wh, *wl;
    cudaGetSymbolAddress((void**)&xh, g_xh);   cudaGetSymbolAddress((void**)&xl, g_xl);
    cudaGetSymbolAddress((void**)&qh, g_qh);   cudaGetSymbolAddress((void**)&ql, g_ql);
    cudaGetSymbolAddress((void**)&kh, g_kh);   cudaGetSymbolAddress((void**)&kl, g_kl);
    cudaGetSymbolAddress((void**)&vh, g_vh);   cudaGetSymbolAddress((void**)&vl, g_vl);
    cudaGetSymbolAddress((void**)&ath, g_ath); cudaGetSymbolAddress((void**)&atl, g_atl);
    cudaGetSymbolAddress((void**)&vih, g_vih); cudaGetSymbolAddress((void**)&vil, g_vil);
    cudaGetSymbolAddress((void**)&wh, g_wh);   cudaGetSymbolAddress((void**)&wl, g_wl);

    cudaFuncSetAttribute(gemm_mma<0>, cudaFuncAttributeMaxDynamicSharedMemorySize, 2 * GSTAGE);
    cudaFuncSetAttribute(gemm_mma<1>, cudaFuncAttributeMaxDynamicSharedMemorySize, 2 * GSTAGE);
    cudaFuncSetAttribute(attn_mma, cudaFuncAttributeMaxDynamicSharedMemorySize, SMEM_ATTN);

    cudaMemcpyAsync(x, query, sizeof(float) * (size_t)M_ * E_, cudaMemcpyDeviceToDevice);
    pack_mask_kernel<<<(B_*S_*S_) / 256, 256>>>(mask);
    split_act_kernel<<<(M_*E_/4) / 256, 256>>>(query, xh, xl);
    split_act_kernel<<<(M_*E_/4) / 256, 256>>>(value, vih, vil);
    dim3 wgrid(32, 32, L_), wblk(32, 8);
    split_wT_kernel<<<wgrid, wblk>>>(Wq, wh, wl, 0);
    split_wT_kernel<<<wgrid, wblk>>>(Wk, wh, wl, 1);
    split_wT_kernel<<<wgrid, wblk>>>(Wv, wh, wl, 2);
    split_wT_kernel<<<wgrid, wblk>>>(Wo, wh, wl, 3);

    dim3 ggrid(8, 64);              // (N/128, M/128)
    dim3 agrid(S_/128, H_, B_);
    for (int l = 0; l < L_; l++) {
        size_t w0 = ((size_t)(l*4 + 0)) << 20;
        size_t w1 = ((size_t)(l*4 + 1)) << 20;
        size_t w2 = ((size_t)(l*4 + 2)) << 20;
        size_t w3 = ((size_t)(l*4 + 3)) << 20;
        gemm_mma<1><<<ggrid, 256, 2*GSTAGE>>>(xh, xl, wh + w0, wl + w0, bq + l*E_,
                                              nullptr, qh, ql);
        gemm_mma<1><<<ggrid, 256, 2*GSTAGE>>>(vih, vil, wh + w1, wl + w1, bk + l*E_,
                                              nullptr, kh, kl);
        gemm_mma<1><<<ggrid, 256, 2*GSTAGE>>>(vih, vil, wh + w2, wl + w2, bv + l*E_,
                                              nullptr, vh, vl);
        attn_mma<<<agrid, 256, SMEM_ATTN>>>(qh, ql, kh, kl, vh, vl, ath, atl);
        gemm_mma<0><<<ggrid, 256, 2*GSTAGE>>>(ath, atl, wh + w3, wl + w3, bo + l*E_,
                                              proj, nullptr, nullptr);
        add_ln_kernel<<<M_, 256>>>(proj, x, gamma + l*E_, beta + l*E_,
                                   (l == L_-1) ? out : x, xh, xl);
    }
}

// round 4
// speedup vs baseline: 3.3919x; 1.0251x over previous
#include <cuda_runtime.h>
#include <cuda_bf16.h>
#include <cstdint>

#define B_ 4
#define S_ 2048
#define E_ 1024
#define H_ 16
#define D_ 64
#define L_ 4
#define M_ (B_*S_)          // 8192 rows
#define PW_ (S_/32)         // 64 mask words per row
#define SCALE_ 0.03125f     // E^-0.5
#define EPS_ 1e-5f

// ---------------- scratch (__device__ globals: allocation-free rule) -------
__device__ float g_x[M_*E_];
__device__ float g_proj[M_*E_];
__device__ unsigned g_pmask[B_*S_*PW_];
__device__ __nv_bfloat16 g_xh[M_*E_],  g_xl[M_*E_];
__device__ __nv_bfloat16 g_qh[M_*E_],  g_ql[M_*E_];
__device__ __nv_bfloat16 g_kh[M_*E_],  g_kl[M_*E_];
__device__ __nv_bfloat16 g_vh[M_*E_],  g_vl[M_*E_];
__device__ __nv_bfloat16 g_ath[M_*E_], g_atl[M_*E_];
__device__ __nv_bfloat16 g_vih[M_*E_], g_vil[M_*E_];
__device__ __nv_bfloat16 g_wh[L_*4*E_*E_];   // weights [N][K] (transposed), bf16 hi
__device__ __nv_bfloat16 g_wl[L_*4*E_*E_];   // bf16 lo

// ============================ portable PTX helpers ==========================
__device__ __forceinline__ uint32_t smem_to_u32(const void* p) {
    uint32_t a;
    asm("{ .reg .u64 t; cvta.to.shared.u64 t, %1; cvt.u32.u64 %0, t; }"
        : "=r"(a) : "l"(p));
    return a;
}
#define SMEM_SWIZZLE_128B(o) ((o) ^ (((o) >> 3) & 0x70))

__device__ __forceinline__ void cp16(uint32_t dst, const void* src) {
    asm volatile("cp.async.cg.shared.global [%0], [%1], 16;" :: "r"(dst), "l"(src) : "memory");
}
#define CP_COMMIT() asm volatile("cp.async.commit_group;" ::: "memory")
#define CP_WAIT0()  asm volatile("cp.async.wait_group 0;" ::: "memory")
#define CP_WAIT1()  asm volatile("cp.async.wait_group 1;" ::: "memory")

__device__ __forceinline__ void ldsm4(uint32_t* r, uint32_t a) {
    asm volatile("ldmatrix.sync.aligned.m8n8.x4.shared.b16 {%0,%1,%2,%3}, [%4];"
        : "=r"(r[0]), "=r"(r[1]), "=r"(r[2]), "=r"(r[3]) : "r"(a));
}
__device__ __forceinline__ void ldsm4t(uint32_t* r, uint32_t a) {
    asm volatile("ldmatrix.sync.aligned.m8n8.x4.trans.shared.b16 {%0,%1,%2,%3}, [%4];"
        : "=r"(r[0]), "=r"(r[1]), "=r"(r[2]), "=r"(r[3]) : "r"(a));
}
// D += A(16x16) * B(16x8), bf16 in, fp32 accum
__device__ __forceinline__ void mma_bf16(float* c, const uint32_t* a, const uint32_t* b) {
    asm volatile("mma.sync.aligned.m16n8k16.row.col.f32.bf16.bf16.f32 "
        "{%0,%1,%2,%3}, {%4,%5,%6,%7}, {%8,%9}, {%0,%1,%2,%3};"
        : "+f"(c[0]), "+f"(c[1]), "+f"(c[2]), "+f"(c[3])
        : "r"(a[0]), "r"(a[1]), "r"(a[2]), "r"(a[3]), "r"(b[0]), "r"(b[1]));
}
__device__ __forceinline__ void split2(float v0, float v1, uint32_t& hi, uint32_t& lo) {
    __nv_bfloat16 h0 = __float2bfloat16(v0), h1 = __float2bfloat16(v1);
    __nv_bfloat16 l0 = __float2bfloat16(v0 - __bfloat162float(h0));
    __nv_bfloat16 l1 = __float2bfloat16(v1 - __bfloat162float(h1));
    __nv_bfloat162 Hh, Ll;
    Hh.x = h0; Hh.y = h1; Ll.x = l0; Ll.y = l1;
    hi = *(uint32_t*)&Hh; lo = *(uint32_t*)&Ll;
}

// ---------------------------------------------------------------------------
__global__ void pack_mask_kernel(const int* __restrict__ mask) {
    unsigned i = blockIdx.x * 256u + threadIdx.x;
    unsigned word = __ballot_sync(0xffffffffu, mask[i] == 1);
    if ((threadIdx.x & 31) == 0) g_pmask[i >> 5] = word;
}

__global__ void split_act_kernel(const float* __restrict__ src,
                                 __nv_bfloat16* __restrict__ hi,
                                 __nv_bfloat16* __restrict__ lo) {
    size_t i = (size_t)blockIdx.x * 256 + threadIdx.x;
    float4 v = ((const float4*)src)[i];
    uint32_t h01, l01, h23, l23;
    split2(v.x, v.y, h01, l01);
    split2(v.z, v.w, h23, l23);
    ((uint2*)hi)[i] = make_uint2(h01, h23);
    ((uint2*)lo)[i] = make_uint2(l01, l23);
}

__global__ void split_wT_kernel(const float* __restrict__ Wbase,
                                __nv_bfloat16* __restrict__ hibase,
                                __nv_bfloat16* __restrict__ lobase, int slot) {
    __shared__ float t[32][33];
    const float* W = Wbase + (size_t)blockIdx.z * E_ * E_;
    size_t dofs = (((size_t)blockIdx.z * 4) + slot) << 20;
    __nv_bfloat16* hi = hibase + dofs;
    __nv_bfloat16* lo = lobase + dofs;
    int bn = blockIdx.x * 32, bk = blockIdx.y * 32;
    int tx = threadIdx.x, ty = threadIdx.y;
    #pragma unroll
    for (int i = 0; i < 32; i += 8)
        t[ty + i][tx] = W[(size_t)(bk + ty + i) * E_ + bn + tx];
    __syncthreads();
    #pragma unroll
    for (int i = 0; i < 32; i += 8) {
        float x = t[tx][ty + i];
        __nv_bfloat16 h = __float2bfloat16(x);
        __nv_bfloat16 l = __float2bfloat16(x - __bfloat162float(h));
        size_t o = (size_t)(bn + ty + i) * E_ + bk + tx;
        hi[o] = h; lo[o] = l;
    }
}

// ---------------------------------------------------------------------------
// bf16x3 MMA GEMM, CTA tile 128x256, K-chunk 64, double-buffered cp.async.
// smem stage: Ah 16K | Al 16K | Wh 32K | Wl 32K = 96K
// ---------------------------------------------------------------------------
#define GS_AL 16384
#define GS_WH 32768
#define GS_WL 65536
#define GSTAGE 98304

__device__ __forceinline__ void gemm_load_stage(uint32_t base,
        const char* gA_h, const char* gA_l, const char* gW_h, const char* gW_l,
        int kc, int tid) {
    size_t co = (size_t)kc * 128;
    #pragma unroll
    for (int i = 0; i < 4; i++) {           // A: 128 rows x 8 seg
        int idx = tid + i * 256;
        int r = idx >> 3, sg = idx & 7;
        uint32_t so = SMEM_SWIZZLE_128B((uint32_t)(r * 128 + sg * 16));
        size_t go = (size_t)r * 2048 + co + sg * 16;
        cp16(base + so, gA_h + go);
        cp16(base + GS_AL + so, gA_l + go);
    }
    #pragma unroll
    for (int i = 0; i < 8; i++) {           // W: 256 rows x 8 seg
        int idx = tid + i * 256;
        int r = idx >> 3, sg = idx & 7;
        uint32_t so = SMEM_SWIZZLE_128B((uint32_t)(r * 128 + sg * 16));
        size_t go = (size_t)r * 2048 + co + sg * 16;
        cp16(base + GS_WH + so, gW_h + go);
        cp16(base + GS_WL + so, gW_l + go);
    }
}

template<int OUT_BF16>
__global__ __launch_bounds__(256, 1)
void gemm_mma(const __nv_bfloat16* __restrict__ Ah, const __nv_bfloat16* __restrict__ Al,
              const __nv_bfloat16* __restrict__ Wh, const __nv_bfloat16* __restrict__ Wl,
              const float* __restrict__ bias, const float* __restrict__ bias2,
              float* __restrict__ C,
              __nv_bfloat16* __restrict__ Ch, __nv_bfloat16* __restrict__ Cl,
              __nv_bfloat16* __restrict__ Ch2, __nv_bfloat16* __restrict__ Cl2) {
    extern __shared__ char smem[];
    const uint32_t sb = smem_to_u32(smem);
    const int tid = threadIdx.x, lane = tid & 31, w = tid >> 5;
    const int bm = blockIdx.y, bn = blockIdx.x;
    const int m0 = (w & 1) * 64, n0 = (w >> 1) * 64;

    const char* gA_h = (const char*)(Ah + (size_t)bm * 128 * E_);
    const char* gA_l = (const char*)(Al + (size_t)bm * 128 * E_);
    const char* gW_h = (const char*)(Wh + (size_t)bn * 256 * E_);
    const char* gW_l = (const char*)(Wl + (size_t)bn * 256 * E_);

    const int arow = m0 + (lane & 15);
    const uint32_t a_kb = (uint32_t)((lane >> 4) * 16);
    const uint32_t axor = (uint32_t)((arow & 7) << 4);
    const int brow = n0 + (lane & 7) + ((lane >> 4) << 3);
    const uint32_t b_kb = (uint32_t)(((lane >> 3) & 1) * 16);
    const uint32_t bxor = (uint32_t)((brow & 7) << 4);

    float c[4][8][4];
    #pragma unroll
    for (int i = 0; i < 4; i++)
        #pragma unroll
        for (int j = 0; j < 8; j++)
            #pragma unroll
            for (int q = 0; q < 4; q++) c[i][j][q] = 0.f;

    gemm_load_stage(sb, gA_h, gA_l, gW_h, gW_l, 0, tid);
    CP_COMMIT();

    for (int kc = 0; kc < 16; kc++) {
        uint32_t stg = sb + (uint32_t)((kc & 1) * GSTAGE);
        CP_WAIT0();
        __syncthreads();            // stage kc visible; all warps done with kc-1
        if (kc + 1 < 16) {
            gemm_load_stage(sb + (uint32_t)(((kc + 1) & 1) * GSTAGE),
                            gA_h, gA_l, gW_h, gW_l, kc + 1, tid);
            CP_COMMIT();
        }
        #pragma unroll
        for (int kk = 0; kk < 4; kk++) {
            uint32_t ah[4][4], al[4][4];
            #pragma unroll
            for (int mt = 0; mt < 4; mt++) {
                uint32_t ra = stg + (uint32_t)((arow + mt * 16) * 128)
                                  + (((uint32_t)(kk * 32) + a_kb) ^ axor);
                ldsm4(ah[mt], ra);
                ldsm4(al[mt], ra + GS_AL);
            }
            #pragma unroll
            for (int p = 0; p < 4; p++) {
                uint32_t bh[4], bl[4];
                uint32_t rb = stg + GS_WH + (uint32_t)((brow + p * 16) * 128)
                                  + (((uint32_t)(kk * 32) + b_kb) ^ bxor);
                ldsm4(bh, rb);
                ldsm4(bl, rb + 32768);
                #pragma unroll
                for (int mt = 0; mt < 4; mt++)
                    #pragma unroll
                    for (int t = 0; t < 2; t++) {
                        int nt = p * 2 + t;
                        mma_bf16(c[mt][nt], ah[mt], &bh[t*2]);
                        mma_bf16(c[mt][nt], ah[mt], &bl[t*2]);
                        mma_bf16(c[mt][nt], al[mt], &bh[t*2]);
                    }
            }
        }
        __syncthreads();
    }

    // epilogue
    const int g = lane >> 2, tg = lane & 3;
    int colbase = bn * 256;
    const float* bias_u = bias;
    __nv_bfloat16 *ChU = Ch, *ClU = Cl;
    if (OUT_BF16 && colbase >= 1024) {
        ChU = Ch2; ClU = Cl2; bias_u = bias2; colbase -= 1024;
    }
    #pragma unroll
    for (int nt = 0; nt < 8; nt++) {
        int col = colbase + n0 + nt * 8 + 2 * tg;
        float b0 = bias_u[col], b1 = bias_u[col + 1];
        #pragma unroll
        for (int mt = 0; mt < 4; mt++) {
            int row = bm * 128 + m0 + mt * 16 + g;
            float v0 = c[mt][nt][0] + b0, v1 = c[mt][nt][1] + b1;
            float v2 = c[mt][nt][2] + b0, v3 = c[mt][nt][3] + b1;
            size_t i0 = (size_t)row * E_ + col;
            size_t i1 = i0 + (size_t)8 * E_;
            if (OUT_BF16) {
                uint32_t h01, l01, h23, l23;
                split2(v0, v1, h01, l01);
                split2(v2, v3, h23, l23);
                *(uint32_t*)(ChU + i0) = h01; *(uint32_t*)(ClU + i0) = l01;
                *(uint32_t*)(ChU + i1) = h23; *(uint32_t*)(ClU + i1) = l23;
            } else {
                *(float2*)(C + i0) = make_float2(v0, v1);
                *(float2*)(C + i1) = make_float2(v2, v3);
            }
        }
    }
}

// ---------------------------------------------------------------------------
// Fused ReLU attention, register-resident scores (flash-style).
// Warp owns 16 q rows x full kv chunk (128). 3-stage KV pipeline.
// smem: Qh 16K | Ql 16K | 3 x (Kh|Kl|Vh|Vl 16K each) = 224K
// ---------------------------------------------------------------------------
#define AQ_L 16384
#define AKV(s) (32768 + (s) * 65536)
#define AKL 16384
#define AVH 32768
#define SMEM_ATTN 229376

__device__ __forceinline__ void attn_load_kv(uint32_t base,
        const char* gK_h, const char* gK_l, const char* gV_h, const char* gV_l,
        int kc, int tid) {
    #pragma unroll
    for (int i = 0; i < 4; i++) {
        int idx = tid + i * 256;
        int r = idx >> 3, sg = idx & 7;
        uint32_t so = SMEM_SWIZZLE_128B((uint32_t)(r * 128 + sg * 16));
        size_t go = (size_t)(kc * 128 + r) * 2048 + sg * 16;
        cp16(base + so,         gK_h + go);
        cp16(base + AKL + so,   gK_l + go);
        cp16(base + AVH + so,   gV_h + go);
        cp16(base + 49152 + so, gV_l + go);
    }
}

__global__ __launch_bounds__(256, 1)
void attn_mma(const __nv_bfloat16* __restrict__ qh, const __nv_bfloat16* __restrict__ ql,
              const __nv_bfloat16* __restrict__ kh, const __nv_bfloat16* __restrict__ kl,
              const __nv_bfloat16* __restrict__ vh, const __nv_bfloat16* __restrict__ vl,
              __nv_bfloat16* __restrict__ oh, __nv_bfloat16* __restrict__ ol) {
    extern __shared__ char smem[];
    const uint32_t sb = smem_to_u32(smem);
    const int tid = threadIdx.x, lane = tid & 31, w = tid >> 5;
    const int qt = blockIdx.x, h = blockIdx.y, b = blockIdx.z;
    const int q0 = qt * 128;
    const int g = lane >> 2, tg = lane & 3;

    const size_t hb = ((size_t)b * S_) * E_ + h * D_;
    const char* gQ_h = (const char*)(qh + hb);
    const char* gQ_l = (const char*)(ql + hb);
    const char* gK_h = (const char*)(kh + hb);
    const char* gK_l = (const char*)(kl + hb);
    const char* gV_h = (const char*)(vh + hb);
    const char* gV_l = (const char*)(vl + hb);
    const unsigned* pm = g_pmask + (size_t)b * S_ * PW_;

    // prologue: group0 = Q + KV0, group1 = KV1
    #pragma unroll
    for (int i = 0; i < 4; i++) {
        int idx = tid + i * 256;
        int r = idx >> 3, sg = idx & 7;
        uint32_t so = SMEM_SWIZZLE_128B((uint32_t)(r * 128 + sg * 16));
        size_t go = (size_t)(q0 + r) * 2048 + sg * 16;
        cp16(sb + so, gQ_h + go);
        cp16(sb + AQ_L + so, gQ_l + go);
    }
    attn_load_kv(sb + AKV(0), gK_h, gK_l, gV_h, gV_l, 0, tid);
    CP_COMMIT();
    attn_load_kv(sb + AKV(1), gK_h, gK_l, gV_h, gV_l, 1, tid);
    CP_COMMIT();

    // fragment addressing
    const int arow = w * 16 + (lane & 15);              // q row within tile
    const uint32_t a_kb = (uint32_t)((lane >> 4) * 16);
    const uint32_t axor = (uint32_t)((arow & 7) << 4);
    const int brow = (lane & 7) + ((lane >> 4) << 3);   // kv row base for K frags
    const uint32_t b_kb = (uint32_t)(((lane >> 3) & 1) * 16);
    const uint32_t bxor = (uint32_t)((brow & 7) << 4);
    const int vrow = lane & 15;
    const uint32_t vdb = (uint32_t)((lane >> 4) * 16);
    const int r0 = q0 + w * 16 + g;                     // this thread's q rows: r0, r0+8

    uint32_t qfh[4][4], qfl[4][4];                      // Q fragments, resident
    float c2[8][4];                                     // O accum (16q x 64d per warp)
    #pragma unroll
    for (int i = 0; i < 8; i++)
        #pragma unroll
        for (int q = 0; q < 4; q++) c2[i][q] = 0.f;

    for (int kc = 0; kc < 16; kc++) {
        uint32_t kv = sb + AKV(kc % 3);
        if (kc < 15) CP_WAIT1(); else CP_WAIT0();
        __syncthreads();            // stage kc visible; all warps done with kc-1
        if (kc + 2 < 16) {
            attn_load_kv(sb + AKV((kc + 2) % 3), gK_h, gK_l, gV_h, gV_l, kc + 2, tid);
            CP_COMMIT();
        }
        if (kc == 0) {              // Q fragments (arrived with group0)
            #pragma unroll
            for (int kk = 0; kk < 4; kk++) {
                uint32_t ra = sb + (uint32_t)(arow * 128)
                                 + (((uint32_t)(kk * 32) + a_kb) ^ axor);
                ldsm4(qfh[kk], ra);
                ldsm4(qfl[kk], ra + AQ_L);
            }
        }

        // ---- stage 1: S(16q x 128kv) = Q @ K^T, fp32 regs ----
        float c1[16][4];
        #pragma unroll
        for (int i = 0; i < 16; i++)
            #pragma unroll
            for (int q = 0; q < 4; q++) c1[i][q] = 0.f;
        #pragma unroll
        for (int kk = 0; kk < 4; kk++) {
            #pragma unroll
            for (int p = 0; p < 8; p++) {
                uint32_t khf[4], klf[4];
                uint32_t rb = kv + (uint32_t)((brow + p * 16) * 128)
                                 + (((uint32_t)(kk * 32) + b_kb) ^ bxor);
                ldsm4(khf, rb);
                ldsm4(klf, rb + AKL);
                #pragma unroll
                for (int t = 0; t < 2; t++) {
                    int nt = p * 2 + t;
                    mma_bf16(c1[nt], qfh[kk], &khf[t*2]);
                    mma_bf16(c1[nt], qfh[kk], &klf[t*2]);
                    mma_bf16(c1[nt], qfl[kk], &khf[t*2]);
                }
            }
        }
        // ---- mask + relu + scale in registers ----
        unsigned mw0[4], mw1[4];
        #pragma unroll
        for (int j = 0; j < 4; j++) {
            mw0[j] = pm[(size_t)r0 * PW_ + kc * 4 + j];
            mw1[j] = pm[(size_t)(r0 + 8) * PW_ + kc * 4 + j];
        }
        #pragma unroll
        for (int nt = 0; nt < 16; nt++) {
            int col = nt * 8 + 2 * tg;
            int wj = col >> 5, bit = col & 31;
            c1[nt][0] = ((mw0[wj] >> bit) & 1u)       ? 0.f : fmaxf(c1[nt][0] * SCALE_, 0.f);
            c1[nt][1] = ((mw0[wj] >> (bit + 1)) & 1u) ? 0.f : fmaxf(c1[nt][1] * SCALE_, 0.f);
            c1[nt][2] = ((mw1[wj] >> bit) & 1u)       ? 0.f : fmaxf(c1[nt][2] * SCALE_, 0.f);
            c1[nt][3] = ((mw1[wj] >> (bit + 1)) & 1u) ? 0.f : fmaxf(c1[nt][3] * SCALE_, 0.f);
        }

        // ---- stage 2: O += S @ V ; S fragments built from c1 in registers ----
        #pragma unroll
        for (int j = 0; j < 8; j++) {
            uint32_t sh[4], sl[4];
            split2(c1[2*j][0],   c1[2*j][1],   sh[0], sl[0]);
            split2(c1[2*j][2],   c1[2*j][3],   sh[1], sl[1]);
            split2(c1[2*j+1][0], c1[2*j+1][1], sh[2], sl[2]);
            split2(c1[2*j+1][2], c1[2*j+1][3], sh[3], sl[3]);
            #pragma unroll
            for (int p = 0; p < 4; p++) {
                uint32_t vhf[4], vlf[4];
                uint32_t off = (uint32_t)((j * 16 + vrow) * 128) + (uint32_t)(p * 32) + vdb;
                uint32_t rb = kv + AVH + SMEM_SWIZZLE_128B(off);
                ldsm4t(vhf, rb);
                ldsm4t(vlf, rb + AKL);
                #pragma unroll
                for (int t = 0; t < 2; t++) {
                    int nt = p * 2 + t;
                    mma_bf16(c2[nt], sh, &vhf[t*2]);
                    mma_bf16(c2[nt], sh, &vlf[t*2]);
                    mma_bf16(c2[nt], sl, &vhf[t*2]);
                }
            }
        }
    }

    // epilogue: O as bf16 hi/lo
    #pragma unroll
    for (int nt = 0; nt < 8; nt++) {
        int col = nt * 8 + 2 * tg;
        size_t i0 = ((size_t)b * S_ + r0) * E_ + h * D_ + col;
        size_t i1 = i0 + (size_t)8 * E_;
        uint32_t h01, l01, h23, l23;
        split2(c2[nt][0], c2[nt][1], h01, l01);
        split2(c2[nt][2], c2[nt][3], h23, l23);
        *(uint32_t*)(oh + i0) = h01; *(uint32_t*)(ol + i0) = l01;
        *(uint32_t*)(oh + i1) = h23; *(uint32_t*)(ol + i1) = l23;
    }
}

// ---------------------------------------------------------------------------
// out = LayerNorm(a + x)*gamma + beta ; also writes bf16 hi/lo of out
// ---------------------------------------------------------------------------
__global__ __launch_bounds__(256)
void add_ln_kernel(const float* __restrict__ a, const float* __restrict__ x,
                   const float* __restrict__ gamma, const float* __restrict__ beta,
                   float* __restrict__ out,
                   __nv_bfloat16* __restrict__ oh, __nv_bfloat16* __restrict__ ol) {
    __shared__ float red[8];
    __shared__ float bcast;
    const int row = blockIdx.x, tid = threadIdx.x;
    const int lane = tid & 31, wid = tid >> 5;
    const float* ap = a + (size_t)row * E_;
    const float* xp = x + (size_t)row * E_;
    float4 va = *(const float4*)(ap + tid * 4);
    float4 vx = *(const float4*)(xp + tid * 4);
    float v0 = va.x + vx.x, v1 = va.y + vx.y, v2 = va.z + vx.z, v3 = va.w + vx.w;
    float s = v0 + v1 + v2 + v3;
    #pragma unroll
    for (int off = 16; off > 0; off >>= 1) s += __shfl_xor_sync(~0u, s, off);
    if (lane == 0) red[wid] = s;
    __syncthreads();
    if (tid == 0) {
        float t = 0;
        #pragma unroll
        for (int i = 0; i < 8; i++) t += red[i];
        bcast = t;
    }
    __syncthreads();
    float mean = bcast * (1.0f / E_);
    float d0 = v0 - mean, d1 = v1 - mean, d2 = v2 - mean, d3 = v3 - mean;
    float vs = d0*d0 + d1*d1 + d2*d2 + d3*d3;
    #pragma unroll
    for (int off = 16; off > 0; off >>= 1) vs += __shfl_xor_sync(~0u, vs, off);
    __syncthreads();
    if (lane == 0) red[wid] = vs;
    __syncthreads();
    if (tid == 0) {
        float t = 0;
        #pragma unroll
        for (int i = 0; i < 8; i++) t += red[i];
        bcast = t;
    }
    __syncthreads();
    float inv = rsqrtf(bcast * (1.0f / E_) + EPS_);
    float4 gq = *(const float4*)(gamma + tid * 4);
    float4 bt = *(const float4*)(beta + tid * 4);
    float o0 = d0*inv*gq.x + bt.x, o1 = d1*inv*gq.y + bt.y;
    float o2 = d2*inv*gq.z + bt.z, o3 = d3*inv*gq.w + bt.w;
    *(float4*)(out + (size_t)row * E_ + tid * 4) = make_float4(o0, o1, o2, o3);
    uint32_t h01, l01, h23, l23;
    split2(o0, o1, h01, l01);
    split2(o2, o3, h23, l23);
    size_t i0 = (size_t)row * E_ + tid * 4;
    *(uint2*)(oh + i0) = make_uint2(h01, h23);
    *(uint2*)(ol + i0) = make_uint2(l01, l23);
}

// ---------------------------------------------------------------------------
extern "C" void kernel_launch(void* const* d_in, const int* in_sizes, int n_in,
                              void* d_out, int out_size) {
    const float* query = (const float*)d_in[0];
    const float* value = (const float*)d_in[1];
    const int*   mask  = (const int*)d_in[2];
    const float* Wq = (const float*)d_in[3];
    const float* Wk = (const float*)d_in[4];
    const float* Wv = (const float*)d_in[5];
    const float* Wo = (const float*)d_in[6];
    const float* bq = (const float*)d_in[7];
    const float* bk = (const float*)d_in[8];
    const float* bv = (const float*)d_in[9];
    const float* bo = (const float*)d_in[10];
    const float* gamma = (const float*)d_in[11];
    const float* beta  = (const float*)d_in[12];
    float* out = (float*)d_out;

    float *x, *proj;
    cudaGetSymbolAddress((void**)&x,    g_x);
    cudaGetSymbolAddress((void**)&proj, g_proj);
    __nv_bfloat16 *xh, *xl, *qh, *ql, *kh, *kl, *vh, *vl, *ath, *atl, *vih, *vil, *wh, *wl;
    cudaGetSymbolAddress((void**)&xh, g_xh);   cudaGetSymbolAddress((void**)&xl, g_xl);
    cudaGetSymbolAddress((void**)&qh, g_qh);   cudaGetSymbolAddress((void**)&ql, g_ql);
    cudaGetSymbolAddress((void**)&kh, g_kh);   cudaGetSymbolAddress((void**)&kl, g_kl);
    cudaGetSymbolAddress((void**)&vh, g_vh);   cudaGetSymbolAddress((void**)&vl, g_vl);
    cudaGetSymbolAddress((void**)&ath, g_ath); cudaGetSymbolAddress((void**)&atl, g_atl);
    cudaGetSymbolAddress((void**)&vih, g_vih); cudaGetSymbolAddress((void**)&vil, g_vil);
    cudaGetSymbolAddress((void**)&wh, g_wh);   cudaGetSymbolAddress((void**)&wl, g_wl);

    cudaFuncSetAttribute(gemm_mma<0>, cudaFuncAttributeMaxDynamicSharedMemorySize, 2 * GSTAGE);
    cudaFuncSetAttribute(gemm_mma<1>, cudaFuncAttributeMaxDynamicSharedMemorySize, 2 * GSTAGE);
    cudaFuncSetAttribute(attn_mma, cudaFuncAttributeMaxDynamicSharedMemorySize, SMEM_ATTN);

    cudaMemcpyAsync(x, query, sizeof(float) * (size_t)M_ * E_, cudaMemcpyDeviceToDevice);
    pack_mask_kernel<<<(B_*S_*S_) / 256, 256>>>(mask);
    split_act_kernel<<<(M_*E_/4) / 256, 256>>>(query, xh, xl);
    split_act_kernel<<<(M_*E_/4) / 256, 256>>>(value, vih, vil);
    dim3 wgrid(32, 32, L_), wblk(32, 8);
    split_wT_kernel<<<wgrid, wblk>>>(Wq, wh, wl, 0);
    split_wT_kernel<<<wgrid, wblk>>>(Wk, wh, wl, 1);
    split_wT_kernel<<<wgrid, wblk>>>(Wv, wh, wl, 2);
    split_wT_kernel<<<wgrid, wblk>>>(Wo, wh, wl, 3);

    dim3 qgrid(4, 64);              // N=1024 (256-wide tiles)
    dim3 kvgrid(8, 64);             // N=2048 fused K|V
    dim3 agrid(S_/128, H_, B_);
    for (int l = 0; l < L_; l++) {
        size_t w0 = ((size_t)(l*4 + 0)) << 20;
        size_t w1 = ((size_t)(l*4 + 1)) << 20;   // Wk, Wv contiguous
        size_t w3 = ((size_t)(l*4 + 3)) << 20;
        gemm_mma<1><<<qgrid, 256, 2*GSTAGE>>>(xh, xl, wh + w0, wl + w0,
                                              bq + l*E_, nullptr, nullptr,
                                              qh, ql, nullptr, nullptr);
        gemm_mma<1><<<kvgrid, 256, 2*GSTAGE>>>(vih, vil, wh + w1, wl + w1,
                                               bk + l*E_, bv + l*E_, nullptr,
                                               kh, kl, vh, vl);
        attn_mma<<<agrid, 256, SMEM_ATTN>>>(qh, ql, kh, kl, vh, vl, ath, atl);
        gemm_mma<0><<<qgrid, 256, 2*GSTAGE>>>(ath, atl, wh + w3, wl + w3,
                                              bo + l*E_, nullptr, proj,
                                              nullptr, nullptr, nullptr, nullptr);
        add_ln_kernel<<<M_, 256>>>(proj, x, gamma + l*E_, beta + l*E_,
                                   (l == L_-1) ? out : x, xh, xl);
    }
}